// round 16
// baseline (speedup 1.0000x reference)
#include <cuda_runtime.h>
#include <cuda_fp16.h>
#include <cstdint>

#define T_TOK 4096
#define DMODEL 768
#define HID 2048
#define NE 8
#define ALPHA 0.05f

#define AST 40
#define BST 72
#define BSTD 136
#define NC_UP (DMODEL / 32)    // 24
#define NC_DN (HID / 32)       // 64 total; 32 per k-split
#define A_TILE (128 * AST)
#define B_TILE (32 * BST)
#define BD_TILE (32 * BSTD)
#define UP_SMEM ((3 * (A_TILE + 2 * B_TILE)) * 2)    // 58368
#define DN_SMEM ((3 * (A_TILE + BD_TILE)) * 2)       // 56832

#define GATE_BLOCKS 512
#define CONVUV_BLOCKS 1536
#define GATHER_BLOCKS T_TOK

// ---------------- scratch ----------------------------------------------------
__device__ int   g_expert[T_TOK];
__device__ float g_gate[T_TOK];
__device__ int   g_counts[NE];
__device__ int   g_off[NE + 1];
__device__ int   g_cursor[NE];
__device__ float g_ce[NE];
__device__ int   g_tok[T_TOK];
__device__ int   g_done;
__device__ __align__(16) __half g_xg[(size_t)T_TOK * DMODEL];
__device__ __align__(16) __half g_h[(size_t)T_TOK * HID];
__device__ __align__(16) __half g_wu16[(size_t)NE * DMODEL * HID];
__device__ __align__(16) __half g_wv16[(size_t)NE * DMODEL * HID];
__device__ __align__(16) __half g_wd16[(size_t)NE * HID * DMODEL];

// ---------------- helpers ----------------------------------------------------
__device__ __forceinline__ uint32_t smem_u32(const void* p) {
    uint32_t a;
    asm("{ .reg .u64 t; cvta.to.shared.u64 t, %1; cvt.u32.u64 %0, t; }" : "=r"(a) : "l"(p));
    return a;
}
__device__ __forceinline__ uint32_t pk(float a, float b) {
    __half2 h = __floats2half2_rn(a, b);
    return *reinterpret_cast<uint32_t*>(&h);
}
__device__ __forceinline__ void cpa16(uint32_t dst, const void* src, bool valid) {
    int sz = valid ? 16 : 0;
    asm volatile("cp.async.cg.shared.global [%0], [%1], 16, %2;\n"
                 :: "r"(dst), "l"(src), "r"(sz) : "memory");
}
#define CP_COMMIT() asm volatile("cp.async.commit_group;" ::: "memory")
#define CP_WAIT1()  asm volatile("cp.async.wait_group 1;" ::: "memory")

#define LDSM_X4(r0, r1, r2, r3, a)                                              \
    asm volatile("ldmatrix.sync.aligned.m8n8.x4.shared.b16 {%0,%1,%2,%3}, [%4];"\
                 : "=r"(r0), "=r"(r1), "=r"(r2), "=r"(r3) : "r"(a))
#define LDSM_X4T(r0, r1, r2, r3, a)                                             \
    asm volatile("ldmatrix.sync.aligned.m8n8.x4.trans.shared.b16 {%0,%1,%2,%3}, [%4];"\
                 : "=r"(r0), "=r"(r1), "=r"(r2), "=r"(r3) : "r"(a))

#define MMA16816(d, a, b0, b1)                                                  \
    asm volatile("mma.sync.aligned.m16n8k16.row.col.f32.f16.f16.f32 "           \
                 "{%0,%1,%2,%3},{%4,%5,%6,%7},{%8,%9},{%0,%1,%2,%3};"           \
                 : "+f"((d)[0]), "+f"((d)[1]), "+f"((d)[2]), "+f"((d)[3])       \
                 : "r"((a)[0]), "r"((a)[1]), "r"((a)[2]), "r"((a)[3]),          \
                   "r"(b0), "r"(b1))

// ---------------- init -------------------------------------------------------
__global__ void init_kernel() {
    int i = threadIdx.x;
    if (i < NE) { g_counts[i] = 0; g_ce[i] = 0.f; }
    if (i == 0) g_done = 0;
}

// ---------------- gate (+ Wu/Wv convert, + inline scan) — R11 ----------------
__global__ void gate_kernel(const float* __restrict__ x,
                            const float* __restrict__ wgw,
                            const float* __restrict__ wgb,
                            const float* __restrict__ Wu,
                            const float* __restrict__ Wv) {
    int tid = threadIdx.x;

    if (blockIdx.x >= GATE_BLOCKS) {
        const size_t n4 = (size_t)NE * DMODEL * HID / 4;
        size_t i0 = (size_t)(blockIdx.x - GATE_BLOCKS) * blockDim.x + tid;
        size_t stride = (size_t)CONVUV_BLOCKS * blockDim.x;
        for (size_t i = i0; i < n4; i += stride) {
            float4 a = ((const float4*)Wu)[i];
            ((uint2*)g_wu16)[i] = make_uint2(pk(a.x, a.y), pk(a.z, a.w));
            float4 b = ((const float4*)Wv)[i];
            ((uint2*)g_wv16)[i] = make_uint2(pk(b.x, b.y), pk(b.z, b.w));
        }
        return;
    }

    __shared__ float s_ce[NE];
    __shared__ int   s_cnt[NE];
    if (tid < NE) { s_ce[tid] = 0.f; s_cnt[tid] = 0; }
    __syncthreads();

    int warp = tid >> 5, lane = tid & 31;
    int t = blockIdx.x * 8 + warp;

    float acc[NE];
#pragma unroll
    for (int e = 0; e < NE; e++) acc[e] = 0.f;
    const float* xr = x + (size_t)t * DMODEL;
    for (int i = lane; i < DMODEL; i += 32) {
        float xv = xr[i];
#pragma unroll
        for (int e = 0; e < NE; e++) acc[e] += xv * wgw[e * DMODEL + i];
    }
#pragma unroll
    for (int e = 0; e < NE; e++)
#pragma unroll
        for (int o = 16; o > 0; o >>= 1) acc[e] += __shfl_xor_sync(0xFFFFFFFFu, acc[e], o);

    if (lane == 0) {
        float mx = -1e30f; int be = 0;
#pragma unroll
        for (int e = 0; e < NE; e++) {
            acc[e] += wgb[e];
            if (acc[e] > mx) { mx = acc[e]; be = e; }
        }
        float p[NE]; float s = 0.f;
#pragma unroll
        for (int e = 0; e < NE; e++) { p[e] = __expf(acc[e] - mx); s += p[e]; }
        float inv = 1.f / s;
#pragma unroll
        for (int e = 0; e < NE; e++) { p[e] *= inv; atomicAdd(&s_ce[e], p[e]); }
        g_expert[t] = be;
        g_gate[t]   = p[be];
        atomicAdd(&s_cnt[be], 1);
    }
    __syncthreads();
    if (tid < NE) { atomicAdd(&g_ce[tid], s_ce[tid]); atomicAdd(&g_counts[tid], s_cnt[tid]); }

    if (tid == 0) {
        __threadfence();
        int prev = atomicAdd(&g_done, 1);
        if (prev == GATE_BLOCKS - 1) {
            int s = 0;
            for (int e = 0; e < NE; e++) {
                int cnt = atomicAdd(&g_counts[e], 0);
                g_off[e] = s; g_cursor[e] = s; s += cnt;
            }
            g_off[NE] = s;
            __threadfence();
        }
    }
}

// ---------------- gather — R11 -----------------------------------------------
__global__ void gather_kernel(const float* __restrict__ x) {
    __shared__ int s_pos;
    int t = blockIdx.x;
    if (threadIdx.x == 0) {
        int e = g_expert[t];
        int pos = atomicAdd(&g_cursor[e], 1);
        g_tok[pos] = t;
        s_pos = pos;
    }
    __syncthreads();
    int pos = s_pos;
    const float4* src = (const float4*)(x + (size_t)t * DMODEL);
    __half2* dst = (__half2*)(g_xg + (size_t)pos * DMODEL);
    for (int i = threadIdx.x; i < DMODEL / 4; i += blockDim.x) {
        float4 v = src[i];
        dst[i * 2 + 0] = __floats2half2_rn(v.x, v.y);
        dst[i * 2 + 1] = __floats2half2_rn(v.z, v.w);
    }
}

// ---------------- up: R11; z==NE slice converts Wd + zeroes out --------------
__global__ __launch_bounds__(256, 2) void up_mma(const float* __restrict__ Wd,
                                                 float* __restrict__ out) {
    if (blockIdx.z == NE) {
        int bid = blockIdx.y * gridDim.x + blockIdx.x;          // 0..1023
        size_t stride = (size_t)gridDim.x * gridDim.y * blockDim.x;
        size_t i0 = (size_t)bid * blockDim.x + threadIdx.x;
        const size_t n4 = (size_t)NE * HID * DMODEL / 4;
        for (size_t i = i0; i < n4; i += stride) {
            float4 c = ((const float4*)Wd)[i];
            ((uint2*)g_wd16)[i] = make_uint2(pk(c.x, c.y), pk(c.z, c.w));
        }
        // zero the y portion of out (dn accumulates with atomicAdd)
        const size_t y4 = (size_t)T_TOK * DMODEL / 4;
        for (size_t i = i0; i < y4; i += stride)
            ((float4*)out)[i] = make_float4(0.f, 0.f, 0.f, 0.f);
        return;
    }

    int e    = blockIdx.z;
    int mEnd = g_off[e + 1];
    int m0   = g_off[e] + blockIdx.y * 128;
    if (m0 >= mEnd) return;
    int n0 = blockIdx.x * 64;

    extern __shared__ __align__(16) __half smem[];
    __half* As = smem;
    __half* Bu = smem + 3 * A_TILE;
    __half* Bv = Bu + 3 * B_TILE;

    int tid = threadIdx.x, lane = tid & 31, wid = tid >> 5;
    int wm = wid & 3, wn = wid >> 2;
    int lg = lane >> 2, lt = lane & 3;

    uint32_t baseA = smem_u32(As), baseU = smem_u32(Bu), baseV = smem_u32(Bv);

    const __half* WuE = g_wu16 + (size_t)e * DMODEL * HID;
    const __half* WvE = g_wv16 + (size_t)e * DMODEL * HID;

    float au[2][4][4], av[2][4][4];
#pragma unroll
    for (int mt = 0; mt < 2; mt++)
#pragma unroll
        for (int nt = 0; nt < 4; nt++)
#pragma unroll
            for (int r = 0; r < 4; r++) { au[mt][nt][r] = 0.f; av[mt][nt][r] = 0.f; }

    int arow = tid >> 2, asg = tid & 3;
    int brow = tid >> 3, bsg = tid & 7;

    auto issue = [&](int c, int st) {
        uint32_t dA = baseA + (uint32_t)(st * A_TILE) * 2;
        uint32_t dU = baseU + (uint32_t)(st * B_TILE) * 2;
        uint32_t dV = baseV + (uint32_t)(st * B_TILE) * 2;
#pragma unroll
        for (int q = 0; q < 2; q++) {
            int row = arow + q * 64;
            int gm = m0 + row;
            bool v = gm < mEnd;
            cpa16(dA + (uint32_t)(row * AST + asg * 8) * 2,
                  &g_xg[(size_t)(v ? gm : m0) * DMODEL + c * 32 + asg * 8], v);
        }
        size_t boff = (size_t)(c * 32 + brow) * HID + n0 + bsg * 8;
        uint32_t soff = (uint32_t)(brow * BST + bsg * 8) * 2;
        cpa16(dU + soff, WuE + boff, true);
        cpa16(dV + soff, WvE + boff, true);
    };
    auto compute = [&](int st) {
        uint32_t sA = baseA + (uint32_t)(st * A_TILE) * 2;
        uint32_t sU = baseU + (uint32_t)(st * B_TILE) * 2;
        uint32_t sV = baseV + (uint32_t)(st * B_TILE) * 2;
#pragma unroll
        for (int s = 0; s < 2; s++) {
            int k0 = s * 16;
            uint32_t a[2][4];
#pragma unroll
            for (int mt = 0; mt < 2; mt++) {
                uint32_t ad = sA + (uint32_t)(((wm * 32 + mt * 16 + (lane & 15)) * AST)
                                              + k0 + (lane >> 4) * 8) * 2;
                LDSM_X4(a[mt][0], a[mt][1], a[mt][2], a[mt][3], ad);
            }
#pragma unroll
            for (int np = 0; np < 2; np++) {
                uint32_t boff = (uint32_t)(((k0 + (lane & 15)) * BST)
                                           + wn * 32 + np * 16 + (lane >> 4) * 8) * 2;
                uint32_t u0, u1, u2, u3, v0, v1, v2, v3;
                LDSM_X4T(u0, u1, u2, u3, sU + boff);
                LDSM_X4T(v0, v1, v2, v3, sV + boff);
#pragma unroll
                for (int mt = 0; mt < 2; mt++) {
                    MMA16816(au[mt][np * 2 + 0], a[mt], u0, u1);
                    MMA16816(au[mt][np * 2 + 1], a[mt], u2, u3);
                    MMA16816(av[mt][np * 2 + 0], a[mt], v0, v1);
                    MMA16816(av[mt][np * 2 + 1], a[mt], v2, v3);
                }
            }
        }
    };

    issue(0, 0); CP_COMMIT();
    issue(1, 1); CP_COMMIT();

    for (int c = 0; c < NC_UP; c++) {
        CP_WAIT1();
        __syncthreads();
        if (c + 2 < NC_UP) issue(c + 2, (c + 2) % 3);
        CP_COMMIT();
        compute(c % 3);
    }

#pragma unroll
    for (int mt = 0; mt < 2; mt++) {
#pragma unroll
        for (int nt = 0; nt < 4; nt++) {
            int row0 = m0 + wm * 32 + mt * 16 + lg;
            int col  = n0 + wn * 32 + nt * 8 + lt * 2;
            if (row0 < mEnd) {
                float u0 = au[mt][nt][0], u1 = au[mt][nt][1];
                float h0 = u0 / (1.f + __expf(-u0)) * av[mt][nt][0];
                float h1 = u1 / (1.f + __expf(-u1)) * av[mt][nt][1];
                *(__half2*)&g_h[(size_t)row0 * HID + col] = __floats2half2_rn(h0, h1);
            }
            int row1 = row0 + 8;
            if (row1 < mEnd) {
                float u2 = au[mt][nt][2], u3 = au[mt][nt][3];
                float h2 = u2 / (1.f + __expf(-u2)) * av[mt][nt][2];
                float h3 = u3 / (1.f + __expf(-u3)) * av[mt][nt][3];
                *(__half2*)&g_h[(size_t)row1 * HID + col] = __floats2half2_rn(h2, h3);
            }
        }
    }
}

// ---------------- down: split-K=2, BN=128, atomicAdd epilogue ----------------
__global__ __launch_bounds__(256, 2) void dn_mma(float* __restrict__ out) {
    int zid = blockIdx.z;
    int e   = zid >> 1;
    int kp  = zid & 1;

    if (zid == 0 && blockIdx.x == 0 && blockIdx.y == 0 && threadIdx.x == 0) {
        float s = 0.f;
        for (int ee = 0; ee < NE; ee++) {
            float me = (float)g_counts[ee] / (float)T_TOK;
            float ce = g_ce[ee] / (float)T_TOK;
            s += me * ce;
        }
        out[(size_t)T_TOK * DMODEL] = ALPHA * NE * s;
    }

    int mEnd = g_off[e + 1];
    int m0   = g_off[e] + blockIdx.y * 128;
    if (m0 >= mEnd) return;
    int n0 = blockIdx.x * 128;
    const int c0 = kp * (NC_DN / 2);          // 0 or 32
    const int cN = NC_DN / 2;                 // 32 chunks per split

    extern __shared__ __align__(16) __half smem[];
    __half* As = smem;
    __half* Bs = smem + 3 * A_TILE;

    int tid = threadIdx.x, lane = tid & 31, wid = tid >> 5;
    int wm = wid & 3, wn = wid >> 2;
    int lg = lane >> 2, lt = lane & 3;

    uint32_t baseA = smem_u32(As), baseB = smem_u32(Bs);

    const __half* WdE = g_wd16 + (size_t)e * HID * DMODEL;

    float acc[2][8][4];
#pragma unroll
    for (int mt = 0; mt < 2; mt++)
#pragma unroll
        for (int nt = 0; nt < 8; nt++)
#pragma unroll
            for (int r = 0; r < 4; r++) acc[mt][nt][r] = 0.f;

    int arow = tid >> 2, asg = tid & 3;
    int brow = tid >> 4, bsg = tid & 15;

    auto issue = [&](int ci, int st) {
        int c = c0 + ci;
        uint32_t dA = baseA + (uint32_t)(st * A_TILE) * 2;
        uint32_t dB = baseB + (uint32_t)(st * BD_TILE) * 2;
#pragma unroll
        for (int q = 0; q < 2; q++) {
            int row = arow + q * 64;
            int gm = m0 + row;
            bool v = gm < mEnd;
            cpa16(dA + (uint32_t)(row * AST + asg * 8) * 2,
                  &g_h[(size_t)(v ? gm : m0) * HID + c * 32 + asg * 8], v);
        }
#pragma unroll
        for (int q = 0; q < 2; q++) {
            int row = brow + q * 16;
            cpa16(dB + (uint32_t)(row * BSTD + bsg * 8) * 2,
                  WdE + (size_t)(c * 32 + row) * DMODEL + n0 + bsg * 8, true);
        }
    };
    auto compute = [&](int st) {
        uint32_t sA = baseA + (uint32_t)(st * A_TILE) * 2;
        uint32_t sB = baseB + (uint32_t)(st * BD_TILE) * 2;
#pragma unroll
        for (int s = 0; s < 2; s++) {
            int k0 = s * 16;
            uint32_t a[2][4];
#pragma unroll
            for (int mt = 0; mt < 2; mt++) {
                uint32_t ad = sA + (uint32_t)(((wm * 32 + mt * 16 + (lane & 15)) * AST)
                                              + k0 + (lane >> 4) * 8) * 2;
                LDSM_X4(a[mt][0], a[mt][1], a[mt][2], a[mt][3], ad);
            }
#pragma unroll
            for (int np = 0; np < 4; np++) {
                uint32_t boff = (uint32_t)(((k0 + (lane & 15)) * BSTD)
                                           + wn * 64 + np * 16 + (lane >> 4) * 8) * 2;
                uint32_t b0, b1, b2, b3;
                LDSM_X4T(b0, b1, b2, b3, sB + boff);
#pragma unroll
                for (int mt = 0; mt < 2; mt++) {
                    MMA16816(acc[mt][np * 2 + 0], a[mt], b0, b1);
                    MMA16816(acc[mt][np * 2 + 1], a[mt], b2, b3);
                }
            }
        }
    };

    issue(0, 0); CP_COMMIT();
    issue(1, 1); CP_COMMIT();

    for (int ci = 0; ci < cN; ci++) {
        CP_WAIT1();
        __syncthreads();
        if (ci + 2 < cN) issue(ci + 2, (ci + 2) % 3);
        CP_COMMIT();
        compute(ci % 3);
    }

#pragma unroll
    for (int mt = 0; mt < 2; mt++) {
#pragma unroll
        for (int nt = 0; nt < 8; nt++) {
            int row0 = m0 + wm * 32 + mt * 16 + lg;
            int col  = n0 + wn * 64 + nt * 8 + lt * 2;
            if (row0 < mEnd) {
                int token = g_tok[row0];
                float gate = g_gate[token];
                float* dst = &out[(size_t)token * DMODEL + col];
                atomicAdd(dst,     acc[mt][nt][0] * gate);
                atomicAdd(dst + 1, acc[mt][nt][1] * gate);
            }
            int row1 = row0 + 8;
            if (row1 < mEnd) {
                int token = g_tok[row1];
                float gate = g_gate[token];
                float* dst = &out[(size_t)token * DMODEL + col];
                atomicAdd(dst,     acc[mt][nt][2] * gate);
                atomicAdd(dst + 1, acc[mt][nt][3] * gate);
            }
        }
    }
}

// ---------------- launch -----------------------------------------------------
extern "C" void kernel_launch(void* const* d_in, const int* in_sizes, int n_in,
                              void* d_out, int out_size) {
    const float* x   = (const float*)d_in[0];
    const float* wgw = (const float*)d_in[1];
    const float* wgb = (const float*)d_in[2];
    const float* Wu  = (const float*)d_in[3];
    const float* Wv  = (const float*)d_in[4];
    const float* Wd  = (const float*)d_in[5];
    float* out = (float*)d_out;

    cudaFuncSetAttribute(up_mma, cudaFuncAttributeMaxDynamicSharedMemorySize, UP_SMEM);
    cudaFuncSetAttribute(dn_mma, cudaFuncAttributeMaxDynamicSharedMemorySize, DN_SMEM);

    init_kernel<<<1, 32>>>();
    gate_kernel<<<GATE_BLOCKS + CONVUV_BLOCKS, 256>>>(x, wgw, wgb, Wu, Wv);
    gather_kernel<<<GATHER_BLOCKS, 192>>>(x);
    up_mma<<<dim3(HID / 64, T_TOK / 128, NE + 1), 256, UP_SMEM>>>(Wd, out);
    dn_mma<<<dim3(DMODEL / 128, T_TOK / 128, NE * 2), 256, DN_SMEM>>>(out);
}

// round 17
// speedup vs baseline: 1.0214x; 1.0214x over previous
#include <cuda_runtime.h>
#include <cuda_fp16.h>
#include <cstdint>

#define T_TOK 4096
#define DMODEL 768
#define HID 2048
#define NE 8
#define ALPHA 0.05f

#define AST 40
#define BST 72
#define BSTD 136
#define NC_UP (DMODEL / 32)
#define NC_DN (HID / 32)
#define A_TILE (128 * AST)
#define B_TILE (32 * BST)
#define BD_TILE (32 * BSTD)
#define UP_SMEM ((3 * (A_TILE + 2 * B_TILE)) * 2)    // 58368
#define DN_SMEM ((3 * (A_TILE + BD_TILE)) * 2)       // 56832

#define GATE_BLOCKS 512
#define CONVUV_BLOCKS 1536
#define DN_TOTAL_CTAS (6 * 32 * NE)                  // 1536

// ---------------- scratch (zero at module load; self-reset each run) --------
__device__ int   g_expert[T_TOK];
__device__ float g_gate[T_TOK];
__device__ int   g_counts[NE];
__device__ int   g_off[NE + 1];
__device__ int   g_cursor[NE];
__device__ float g_ce[NE];
__device__ int   g_tok[T_TOK];
__device__ int   g_done;
__device__ int   g_dn_done;
__device__ __align__(16) __half g_xg[(size_t)T_TOK * DMODEL];
__device__ __align__(16) __half g_h[(size_t)T_TOK * HID];
__device__ __align__(16) __half g_wu16[(size_t)NE * DMODEL * HID];
__device__ __align__(16) __half g_wv16[(size_t)NE * DMODEL * HID];
__device__ __align__(16) __half g_wd16[(size_t)NE * HID * DMODEL];

// ---------------- helpers ----------------------------------------------------
__device__ __forceinline__ uint32_t smem_u32(const void* p) {
    uint32_t a;
    asm("{ .reg .u64 t; cvta.to.shared.u64 t, %1; cvt.u32.u64 %0, t; }" : "=r"(a) : "l"(p));
    return a;
}
__device__ __forceinline__ uint32_t pk(float a, float b) {
    __half2 h = __floats2half2_rn(a, b);
    return *reinterpret_cast<uint32_t*>(&h);
}
__device__ __forceinline__ void cpa16(uint32_t dst, const void* src, bool valid) {
    int sz = valid ? 16 : 0;
    asm volatile("cp.async.cg.shared.global [%0], [%1], 16, %2;\n"
                 :: "r"(dst), "l"(src), "r"(sz) : "memory");
}
#define CP_COMMIT() asm volatile("cp.async.commit_group;" ::: "memory")
#define CP_WAIT1()  asm volatile("cp.async.wait_group 1;" ::: "memory")

#define LDSM_X4(r0, r1, r2, r3, a)                                              \
    asm volatile("ldmatrix.sync.aligned.m8n8.x4.shared.b16 {%0,%1,%2,%3}, [%4];"\
                 : "=r"(r0), "=r"(r1), "=r"(r2), "=r"(r3) : "r"(a))
#define LDSM_X4T(r0, r1, r2, r3, a)                                             \
    asm volatile("ldmatrix.sync.aligned.m8n8.x4.trans.shared.b16 {%0,%1,%2,%3}, [%4];"\
                 : "=r"(r0), "=r"(r1), "=r"(r2), "=r"(r3) : "r"(a))

#define MMA16816(d, a, b0, b1)                                                  \
    asm volatile("mma.sync.aligned.m16n8k16.row.col.f32.f16.f16.f32 "           \
                 "{%0,%1,%2,%3},{%4,%5,%6,%7},{%8,%9},{%0,%1,%2,%3};"           \
                 : "+f"((d)[0]), "+f"((d)[1]), "+f"((d)[2]), "+f"((d)[3])       \
                 : "r"((a)[0]), "r"((a)[1]), "r"((a)[2]), "r"((a)[3]),          \
                   "r"(b0), "r"(b1))

// ---------------- gate (+ Wu/Wv convert, + inline scan) — R11 ----------------
__global__ void gate_kernel(const float* __restrict__ x,
                            const float* __restrict__ wgw,
                            const float* __restrict__ wgb,
                            const float* __restrict__ Wu,
                            const float* __restrict__ Wv) {
    int tid = threadIdx.x;

    if (blockIdx.x >= GATE_BLOCKS) {
        const size_t n4 = (size_t)NE * DMODEL * HID / 4;
        size_t i0 = (size_t)(blockIdx.x - GATE_BLOCKS) * blockDim.x + tid;
        size_t stride = (size_t)CONVUV_BLOCKS * blockDim.x;
        for (size_t i = i0; i < n4; i += stride) {
            float4 a = ((const float4*)Wu)[i];
            ((uint2*)g_wu16)[i] = make_uint2(pk(a.x, a.y), pk(a.z, a.w));
            float4 b = ((const float4*)Wv)[i];
            ((uint2*)g_wv16)[i] = make_uint2(pk(b.x, b.y), pk(b.z, b.w));
        }
        return;
    }

    __shared__ float s_ce[NE];
    __shared__ int   s_cnt[NE];
    if (tid < NE) { s_ce[tid] = 0.f; s_cnt[tid] = 0; }
    __syncthreads();

    int warp = tid >> 5, lane = tid & 31;
    int t = blockIdx.x * 8 + warp;

    float acc[NE];
#pragma unroll
    for (int e = 0; e < NE; e++) acc[e] = 0.f;
    const float* xr = x + (size_t)t * DMODEL;
    for (int i = lane; i < DMODEL; i += 32) {
        float xv = xr[i];
#pragma unroll
        for (int e = 0; e < NE; e++) acc[e] += xv * wgw[e * DMODEL + i];
    }
#pragma unroll
    for (int e = 0; e < NE; e++)
#pragma unroll
        for (int o = 16; o > 0; o >>= 1) acc[e] += __shfl_xor_sync(0xFFFFFFFFu, acc[e], o);

    if (lane == 0) {
        float mx = -1e30f; int be = 0;
#pragma unroll
        for (int e = 0; e < NE; e++) {
            acc[e] += wgb[e];
            if (acc[e] > mx) { mx = acc[e]; be = e; }
        }
        float p[NE]; float s = 0.f;
#pragma unroll
        for (int e = 0; e < NE; e++) { p[e] = __expf(acc[e] - mx); s += p[e]; }
        float inv = 1.f / s;
#pragma unroll
        for (int e = 0; e < NE; e++) { p[e] *= inv; atomicAdd(&s_ce[e], p[e]); }
        g_expert[t] = be;
        g_gate[t]   = p[be];
        atomicAdd(&s_cnt[be], 1);
    }
    __syncthreads();
    if (tid < NE) { atomicAdd(&g_ce[tid], s_ce[tid]); atomicAdd(&g_counts[tid], s_cnt[tid]); }

    if (tid == 0) {
        __threadfence();
        int prev = atomicAdd(&g_done, 1);
        if (prev == GATE_BLOCKS - 1) {
            int s = 0;
            for (int e = 0; e < NE; e++) {
                int cnt = atomicAdd(&g_counts[e], 0);
                g_off[e] = s; g_cursor[e] = s; s += cnt;
            }
            g_off[NE] = s;
            __threadfence();
        }
    }
}

// ---------------- gather: warp-per-token (MLP=3 per lane) --------------------
__global__ void gather_kernel(const float* __restrict__ x) {
    __shared__ int s_pos[8];
    int tid = threadIdx.x, warp = tid >> 5, lane = tid & 31;
    int t = blockIdx.x * 8 + warp;
    if (lane == 0) {
        int e = g_expert[t];
        int pos = atomicAdd(&g_cursor[e], 1);
        g_tok[pos] = t;
        s_pos[warp] = pos;
    }
    __syncwarp();
    int pos = s_pos[warp];
    const float4* src = (const float4*)(x + (size_t)t * DMODEL);
    __half2*      dst = (__half2*)(g_xg + (size_t)pos * DMODEL);
    // 192 float4 per token, 32 lanes -> 6 per lane; batch loads for MLP
    float4 v0 = src[lane];
    float4 v1 = src[lane + 32];
    float4 v2 = src[lane + 64];
    float4 v3 = src[lane + 96];
    float4 v4 = src[lane + 128];
    float4 v5 = src[lane + 160];
    dst[lane * 2 + 0]   = __floats2half2_rn(v0.x, v0.y);
    dst[lane * 2 + 1]   = __floats2half2_rn(v0.z, v0.w);
    dst[(lane + 32) * 2 + 0] = __floats2half2_rn(v1.x, v1.y);
    dst[(lane + 32) * 2 + 1] = __floats2half2_rn(v1.z, v1.w);
    dst[(lane + 64) * 2 + 0] = __floats2half2_rn(v2.x, v2.y);
    dst[(lane + 64) * 2 + 1] = __floats2half2_rn(v2.z, v2.w);
    dst[(lane + 96) * 2 + 0] = __floats2half2_rn(v3.x, v3.y);
    dst[(lane + 96) * 2 + 1] = __floats2half2_rn(v3.z, v3.w);
    dst[(lane + 128) * 2 + 0] = __floats2half2_rn(v4.x, v4.y);
    dst[(lane + 128) * 2 + 1] = __floats2half2_rn(v4.z, v4.w);
    dst[(lane + 160) * 2 + 0] = __floats2half2_rn(v5.x, v5.y);
    dst[(lane + 160) * 2 + 1] = __floats2half2_rn(v5.z, v5.w);
}

// ---------------- up: R11; z==NE slice converts Wd ---------------------------
__global__ __launch_bounds__(256, 2) void up_mma(const float* __restrict__ Wd) {
    if (blockIdx.z == NE) {
        const size_t n4 = (size_t)NE * HID * DMODEL / 4;
        int bid = blockIdx.y * gridDim.x + blockIdx.x;
        size_t i0 = (size_t)bid * blockDim.x + threadIdx.x;
        size_t stride = (size_t)gridDim.x * gridDim.y * blockDim.x;
        for (size_t i = i0; i < n4; i += stride) {
            float4 c = ((const float4*)Wd)[i];
            ((uint2*)g_wd16)[i] = make_uint2(pk(c.x, c.y), pk(c.z, c.w));
        }
        return;
    }

    int e    = blockIdx.z;
    int mEnd = g_off[e + 1];
    int m0   = g_off[e] + blockIdx.y * 128;
    if (m0 >= mEnd) return;
    int n0 = blockIdx.x * 64;

    extern __shared__ __align__(16) __half smem[];
    __half* As = smem;
    __half* Bu = smem + 3 * A_TILE;
    __half* Bv = Bu + 3 * B_TILE;

    int tid = threadIdx.x, lane = tid & 31, wid = tid >> 5;
    int wm = wid & 3, wn = wid >> 2;
    int lg = lane >> 2, lt = lane & 3;

    uint32_t baseA = smem_u32(As), baseU = smem_u32(Bu), baseV = smem_u32(Bv);

    const __half* WuE = g_wu16 + (size_t)e * DMODEL * HID;
    const __half* WvE = g_wv16 + (size_t)e * DMODEL * HID;

    float au[2][4][4], av[2][4][4];
#pragma unroll
    for (int mt = 0; mt < 2; mt++)
#pragma unroll
        for (int nt = 0; nt < 4; nt++)
#pragma unroll
            for (int r = 0; r < 4; r++) { au[mt][nt][r] = 0.f; av[mt][nt][r] = 0.f; }

    int arow = tid >> 2, asg = tid & 3;
    int brow = tid >> 3, bsg = tid & 7;

    auto issue = [&](int c, int st) {
        uint32_t dA = baseA + (uint32_t)(st * A_TILE) * 2;
        uint32_t dU = baseU + (uint32_t)(st * B_TILE) * 2;
        uint32_t dV = baseV + (uint32_t)(st * B_TILE) * 2;
#pragma unroll
        for (int q = 0; q < 2; q++) {
            int row = arow + q * 64;
            int gm = m0 + row;
            bool v = gm < mEnd;
            cpa16(dA + (uint32_t)(row * AST + asg * 8) * 2,
                  &g_xg[(size_t)(v ? gm : m0) * DMODEL + c * 32 + asg * 8], v);
        }
        size_t boff = (size_t)(c * 32 + brow) * HID + n0 + bsg * 8;
        uint32_t soff = (uint32_t)(brow * BST + bsg * 8) * 2;
        cpa16(dU + soff, WuE + boff, true);
        cpa16(dV + soff, WvE + boff, true);
    };
    auto compute = [&](int st) {
        uint32_t sA = baseA + (uint32_t)(st * A_TILE) * 2;
        uint32_t sU = baseU + (uint32_t)(st * B_TILE) * 2;
        uint32_t sV = baseV + (uint32_t)(st * B_TILE) * 2;
#pragma unroll
        for (int s = 0; s < 2; s++) {
            int k0 = s * 16;
            uint32_t a[2][4];
#pragma unroll
            for (int mt = 0; mt < 2; mt++) {
                uint32_t ad = sA + (uint32_t)(((wm * 32 + mt * 16 + (lane & 15)) * AST)
                                              + k0 + (lane >> 4) * 8) * 2;
                LDSM_X4(a[mt][0], a[mt][1], a[mt][2], a[mt][3], ad);
            }
#pragma unroll
            for (int np = 0; np < 2; np++) {
                uint32_t boff = (uint32_t)(((k0 + (lane & 15)) * BST)
                                           + wn * 32 + np * 16 + (lane >> 4) * 8) * 2;
                uint32_t u0, u1, u2, u3, v0, v1, v2, v3;
                LDSM_X4T(u0, u1, u2, u3, sU + boff);
                LDSM_X4T(v0, v1, v2, v3, sV + boff);
#pragma unroll
                for (int mt = 0; mt < 2; mt++) {
                    MMA16816(au[mt][np * 2 + 0], a[mt], u0, u1);
                    MMA16816(au[mt][np * 2 + 1], a[mt], u2, u3);
                    MMA16816(av[mt][np * 2 + 0], a[mt], v0, v1);
                    MMA16816(av[mt][np * 2 + 1], a[mt], v2, v3);
                }
            }
        }
    };

    issue(0, 0); CP_COMMIT();
    issue(1, 1); CP_COMMIT();

    for (int c = 0; c < NC_UP; c++) {
        CP_WAIT1();
        __syncthreads();
        if (c + 2 < NC_UP) issue(c + 2, (c + 2) % 3);
        CP_COMMIT();
        compute(c % 3);
    }

#pragma unroll
    for (int mt = 0; mt < 2; mt++) {
#pragma unroll
        for (int nt = 0; nt < 4; nt++) {
            int row0 = m0 + wm * 32 + mt * 16 + lg;
            int col  = n0 + wn * 32 + nt * 8 + lt * 2;
            if (row0 < mEnd) {
                float u0 = au[mt][nt][0], u1 = au[mt][nt][1];
                float h0 = u0 / (1.f + __expf(-u0)) * av[mt][nt][0];
                float h1 = u1 / (1.f + __expf(-u1)) * av[mt][nt][1];
                *(__half2*)&g_h[(size_t)row0 * HID + col] = __floats2half2_rn(h0, h1);
            }
            int row1 = row0 + 8;
            if (row1 < mEnd) {
                float u2 = au[mt][nt][2], u3 = au[mt][nt][3];
                float h2 = u2 / (1.f + __expf(-u2)) * av[mt][nt][2];
                float h3 = u3 / (1.f + __expf(-u3)) * av[mt][nt][3];
                *(__half2*)&g_h[(size_t)row1 * HID + col] = __floats2half2_rn(h2, h3);
            }
        }
    }
}

// ---------------- down: BN=128 (+ inline aux, + state self-reset) ------------
__global__ __launch_bounds__(256, 2) void dn_mma(float* __restrict__ out) {
    if (blockIdx.x == 0 && blockIdx.y == 0 && blockIdx.z == 0 && threadIdx.x == 0) {
        float s = 0.f;
        for (int e = 0; e < NE; e++) {
            float me = (float)g_counts[e] / (float)T_TOK;
            float ce = g_ce[e] / (float)T_TOK;
            s += me * ce;
        }
        out[(size_t)T_TOK * DMODEL] = ALPHA * NE * s;
    }

    int e    = blockIdx.z;
    int mEnd = g_off[e + 1];
    int m0   = g_off[e] + blockIdx.y * 128;
    int n0 = blockIdx.x * 128;

    if (m0 < mEnd) {
        extern __shared__ __align__(16) __half smem[];
        __half* As = smem;
        __half* Bs = smem + 3 * A_TILE;

        int tid = threadIdx.x, lane = tid & 31, wid = tid >> 5;
        int wm = wid & 3, wn = wid >> 2;
        int lg = lane >> 2, lt = lane & 3;

        uint32_t baseA = smem_u32(As), baseB = smem_u32(Bs);

        const __half* WdE = g_wd16 + (size_t)e * HID * DMODEL;

        float acc[2][8][4];
#pragma unroll
        for (int mt = 0; mt < 2; mt++)
#pragma unroll
            for (int nt = 0; nt < 8; nt++)
#pragma unroll
                for (int r = 0; r < 4; r++) acc[mt][nt][r] = 0.f;

        int arow = tid >> 2, asg = tid & 3;
        int brow = tid >> 4, bsg = tid & 15;

        auto issue = [&](int c, int st) {
            uint32_t dA = baseA + (uint32_t)(st * A_TILE) * 2;
            uint32_t dB = baseB + (uint32_t)(st * BD_TILE) * 2;
#pragma unroll
            for (int q = 0; q < 2; q++) {
                int row = arow + q * 64;
                int gm = m0 + row;
                bool v = gm < mEnd;
                cpa16(dA + (uint32_t)(row * AST + asg * 8) * 2,
                      &g_h[(size_t)(v ? gm : m0) * HID + c * 32 + asg * 8], v);
            }
#pragma unroll
            for (int q = 0; q < 2; q++) {
                int row = brow + q * 16;
                cpa16(dB + (uint32_t)(row * BSTD + bsg * 8) * 2,
                      WdE + (size_t)(c * 32 + row) * DMODEL + n0 + bsg * 8, true);
            }
        };
        auto compute = [&](int st) {
            uint32_t sA = baseA + (uint32_t)(st * A_TILE) * 2;
            uint32_t sB = baseB + (uint32_t)(st * BD_TILE) * 2;
#pragma unroll
            for (int s = 0; s < 2; s++) {
                int k0 = s * 16;
                uint32_t a[2][4];
#pragma unroll
                for (int mt = 0; mt < 2; mt++) {
                    uint32_t ad = sA + (uint32_t)(((wm * 32 + mt * 16 + (lane & 15)) * AST)
                                                  + k0 + (lane >> 4) * 8) * 2;
                    LDSM_X4(a[mt][0], a[mt][1], a[mt][2], a[mt][3], ad);
                }
#pragma unroll
                for (int np = 0; np < 4; np++) {
                    uint32_t boff = (uint32_t)(((k0 + (lane & 15)) * BSTD)
                                               + wn * 64 + np * 16 + (lane >> 4) * 8) * 2;
                    uint32_t b0, b1, b2, b3;
                    LDSM_X4T(b0, b1, b2, b3, sB + boff);
#pragma unroll
                    for (int mt = 0; mt < 2; mt++) {
                        MMA16816(acc[mt][np * 2 + 0], a[mt], b0, b1);
                        MMA16816(acc[mt][np * 2 + 1], a[mt], b2, b3);
                    }
                }
            }
        };

        issue(0, 0); CP_COMMIT();
        issue(1, 1); CP_COMMIT();

        for (int c = 0; c < NC_DN; c++) {
            CP_WAIT1();
            __syncthreads();
            if (c + 2 < NC_DN) issue(c + 2, (c + 2) % 3);
            CP_COMMIT();
            compute(c % 3);
        }

#pragma unroll
        for (int mt = 0; mt < 2; mt++) {
#pragma unroll
            for (int nt = 0; nt < 8; nt++) {
                int row0 = m0 + wm * 32 + mt * 16 + lg;
                int col  = n0 + wn * 64 + nt * 8 + lt * 2;
                if (row0 < mEnd) {
                    int token = g_tok[row0];
                    float gate = g_gate[token];
                    *(float2*)&out[(size_t)token * DMODEL + col] =
                        make_float2(acc[mt][nt][0] * gate, acc[mt][nt][1] * gate);
                }
                int row1 = row0 + 8;
                if (row1 < mEnd) {
                    int token = g_tok[row1];
                    float gate = g_gate[token];
                    *(float2*)&out[(size_t)token * DMODEL + col] =
                        make_float2(acc[mt][nt][2] * gate, acc[mt][nt][3] * gate);
                }
            }
        }
        __syncthreads();
    }

    // ---- state self-reset: last dn CTA to finish resets launch state -------
    if (threadIdx.x == 0) {
        __threadfence();
        int prev = atomicAdd(&g_dn_done, 1);
        if (prev == DN_TOTAL_CTAS - 1) {
            for (int ee = 0; ee < NE; ee++) { g_counts[ee] = 0; g_ce[ee] = 0.f; }
            g_done = 0;
            g_dn_done = 0;
            __threadfence();
        }
    }
}

// ---------------- launch -----------------------------------------------------
extern "C" void kernel_launch(void* const* d_in, const int* in_sizes, int n_in,
                              void* d_out, int out_size) {
    const float* x   = (const float*)d_in[0];
    const float* wgw = (const float*)d_in[1];
    const float* wgb = (const float*)d_in[2];
    const float* Wu  = (const float*)d_in[3];
    const float* Wv  = (const float*)d_in[4];
    const float* Wd  = (const float*)d_in[5];
    float* out = (float*)d_out;

    cudaFuncSetAttribute(up_mma, cudaFuncAttributeMaxDynamicSharedMemorySize, UP_SMEM);
    cudaFuncSetAttribute(dn_mma, cudaFuncAttributeMaxDynamicSharedMemorySize, DN_SMEM);

    gate_kernel<<<GATE_BLOCKS + CONVUV_BLOCKS, 256>>>(x, wgw, wgb, Wu, Wv);
    gather_kernel<<<T_TOK / 8, 256>>>(x);
    up_mma<<<dim3(HID / 64, T_TOK / 128, NE + 1), 256, UP_SMEM>>>(Wd);
    dn_mma<<<dim3(DMODEL / 128, T_TOK / 128, NE), 256, DN_SMEM>>>(out);
}